// round 2
// baseline (speedup 1.0000x reference)
#include <cuda_runtime.h>
#include <math.h>

// ------------------------------------------------------------------
// Shapes: x [B=4, C=32, H=64, W=64, D=64] f32
// Modes: kh,kw in {0..11} u {52..63} (24 each), kd in {0..11}
// out [4,32,64,64,64] f32
// ------------------------------------------------------------------

#define Bn 4
#define Cn 32
#define On 32
#define Hn 64
#define Wn 64
#define Dn 64
#define MD 12            // kd modes
#define MHW 24           // kh/kw modes (12 low + 12 high)

// scratch buffers (interleaved complex)
__device__ float2 g_X1[Bn*Cn*Hn*MD*Wn];      // [(b c h)][kd][w]      6,291,456
__device__ float2 g_X2[Bn*Cn*MHW*MD*Hn];     // [(b c)][kw][kd][h]    2,359,296
__device__ float2 g_X3[Bn*Cn*MD*MHW*MHW];    // [(b c)][kd][kh][kw]     884,736
__device__ float2 g_Y [Bn*On*MD*MHW*MHW];    // [(b o)][kd][kh][kw]     884,736
__device__ float2 g_Z1[Bn*On*Hn*MD*MHW];     // [(b o h)][kd][kw]     2,359,296
__device__ float2 g_Z2[Bn*On*Hn*Wn*MD];      // [(b o h)][w][kd]      6,291,456
__device__ float  g_CFT[256*576];
__device__ float  g_CORR[Bn*On*Dn];

// E[t] = (cos(2*pi*t/64), sin(2*pi*t/64))
__device__ __forceinline__ void initE(float2* E, int t, int nthr) {
    for (int i = t; i < 64; i += nthr)
        E[i] = make_float2(cospif(i * (1.0f/32.0f)), sinpif(i * (1.0f/32.0f)));
}

// ---------------- F1: real DFT along D (12 modes) ----------------
// block = (b*C+c)*64+h, 256 threads
__global__ void k_f1(const float* __restrict__ x) {
    __shared__ float  xt[64*65];
    __shared__ float2 E[64];
    int t = threadIdx.x;
    initE(E, t, 256);
    const float* xr = x + (size_t)blockIdx.x * 4096;
    for (int i = t; i < 4096; i += 256)
        xt[(i >> 6) * 65 + (i & 63)] = xr[i];
    __syncthreads();
    int w = t >> 2, j = t & 3, kd0 = j * 3;
    float re0=0,re1=0,re2=0,im0=0,im1=0,im2=0;
    #pragma unroll 4
    for (int d = 0; d < 64; d++) {
        float xv = xt[w*65 + d];
        float2 e0 = E[( kd0      * d) & 63];
        float2 e1 = E[((kd0 + 1) * d) & 63];
        float2 e2 = E[((kd0 + 2) * d) & 63];
        re0 = fmaf(xv, e0.x, re0); im0 = fmaf(-xv, e0.y, im0);
        re1 = fmaf(xv, e1.x, re1); im1 = fmaf(-xv, e1.y, im1);
        re2 = fmaf(xv, e2.x, re2); im2 = fmaf(-xv, e2.y, im2);
    }
    float2* o = g_X1 + (size_t)blockIdx.x * (MD * 64);
    o[(kd0    ) * 64 + w] = make_float2(re0, im0);
    o[(kd0 + 1) * 64 + w] = make_float2(re1, im1);
    o[(kd0 + 2) * 64 + w] = make_float2(re2, im2);
}

// ---------------- F2: DFT along W (24 modes) ----------------
// block = (b*C+c)*12+kd, 256 threads
__global__ void k_f2() {
    __shared__ float2 A[64*65];   // [h][w]
    __shared__ float2 E[64];
    int t = threadIdx.x;
    initE(E, t, 256);
    int bc = blockIdx.x / MD, kd = blockIdx.x % MD;
    const float2* src = g_X1 + (size_t)bc * 64 * (MD*64) + kd * 64;
    for (int i = t; i < 4096; i += 256) {
        int h = i >> 6, w = i & 63;
        A[h*65 + w] = src[(size_t)h * (MD*64) + w];
    }
    __syncthreads();
    int h = t & 63, kwg = t >> 6;
    int kwi[6];
    float2 acc[6];
    #pragma unroll
    for (int u = 0; u < 6; u++) {
        int kw = kwg * 6 + u;
        kwi[u] = kw + (kw >= 12 ? 40 : 0);
        acc[u] = make_float2(0.f, 0.f);
    }
    for (int w = 0; w < 64; w++) {
        float2 a = A[h*65 + w];
        #pragma unroll
        for (int u = 0; u < 6; u++) {
            float2 e = E[(kwi[u] * w) & 63];
            acc[u].x = fmaf(a.x, e.x, fmaf( a.y, e.y, acc[u].x));
            acc[u].y = fmaf(a.y, e.x, fmaf(-a.x, e.y, acc[u].y));
        }
    }
    #pragma unroll
    for (int u = 0; u < 6; u++) {
        int kw = kwg * 6 + u;
        g_X2[((size_t)(bc * MHW + kw) * MD + kd) * 64 + h] = acc[u];
    }
}

// ---------------- F3: DFT along H (24 modes) ----------------
// block = (b*C+c)*12+kd, 288 threads
__global__ void k_f3() {
    __shared__ float2 Bt[24*65];  // [kw][h]
    __shared__ float2 E[64];
    int t = threadIdx.x;
    initE(E, t, 288);
    int bc = blockIdx.x / MD, kd = blockIdx.x % MD;
    for (int i = t; i < 24*64; i += 288) {
        int kw = i >> 6, h = i & 63;
        Bt[kw*65 + h] = g_X2[((size_t)(bc * MHW + kw) * MD + kd) * 64 + h];
    }
    __syncthreads();
    int kw = t % 24, kh2 = t / 24;       // kh2 in 0..11
    int khi0 = kh2, khi1 = kh2 + 52;
    float2 a0 = make_float2(0,0), a1 = make_float2(0,0);
    for (int h = 0; h < 64; h++) {
        float2 a = Bt[kw*65 + h];
        float2 e0 = E[(khi0 * h) & 63];
        float2 e1 = E[(khi1 * h) & 63];
        a0.x = fmaf(a.x, e0.x, fmaf( a.y, e0.y, a0.x));
        a0.y = fmaf(a.y, e0.x, fmaf(-a.x, e0.y, a0.y));
        a1.x = fmaf(a.x, e1.x, fmaf( a.y, e1.y, a1.x));
        a1.y = fmaf(a.y, e1.x, fmaf(-a.x, e1.y, a1.y));
    }
    float2* o = g_X3 + (size_t)(bc * MD + kd) * 576;
    o[ kh2       * 24 + kw] = a0;
    o[(kh2 + 12) * 24 + kw] = a1;
}

// ---------------- MIX: per-mode 32x32 complex matvec ----------------
// block = (q, m1, m2): 4*12*12 = 576 blocks, 128 threads, dynamic smem
__global__ void k_mix(const float* __restrict__ w1re, const float* __restrict__ w1im,
                      const float* __restrict__ w2re, const float* __restrict__ w2im,
                      const float* __restrict__ w3re, const float* __restrict__ w3im,
                      const float* __restrict__ w4re, const float* __restrict__ w4im) {
    extern __shared__ float sm[];
    float*  Wre = sm;                         // [i][kd][o] : (i*12+kd)*32+o
    float*  Wim = sm + 12288;
    float2* X3s = (float2*)(sm + 24576);      // [(b*32+i)*12+kd]
    const float* wres[4] = {w1re, w2re, w3re, w4re};
    const float* wims[4] = {w1im, w2im, w3im, w4im};

    int t = threadIdx.x;
    int q = blockIdx.x / 144, mm = blockIdx.x % 144;
    int m1 = mm / 12, m2 = mm % 12;
    int kh = m1 + (q & 1) * 12;
    int kw = m2 + ((q >> 1) & 1) * 12;
    int mhw = kh * 24 + kw;
    const float* wre = wres[q];
    const float* wim = wims[q];

    for (int idx = t; idx < 12288; idx += 128) {
        int io = idx / 12, kd = idx % 12;
        int i = io >> 5, o = io & 31;
        size_t g = (size_t)io * 1728 + m1 * 144 + m2 * 12 + kd;
        Wre[(i*12 + kd) * 32 + o] = wre[g];
        Wim[(i*12 + kd) * 32 + o] = wim[g];
    }
    for (int idx = t; idx < 1536; idx += 128)
        X3s[idx] = g_X3[(size_t)idx * 576 + mhw];
    __syncthreads();

    int b = t >> 5, o = t & 31;
    float2 acc[12];
    #pragma unroll
    for (int kd = 0; kd < 12; kd++) acc[kd] = make_float2(0.f, 0.f);
    for (int i = 0; i < 32; i++) {
        int xbase = (b * 32 + i) * 12;
        int wbase = i * 384 + o;
        #pragma unroll
        for (int kd = 0; kd < 12; kd++) {
            float2 a = X3s[xbase + kd];
            float wr = Wre[wbase + kd * 32];
            float wi = Wim[wbase + kd * 32];
            acc[kd].x = fmaf(a.x, wr, fmaf(-a.y, wi, acc[kd].x));
            acc[kd].y = fmaf(a.x, wi, fmaf( a.y, wr, acc[kd].y));
        }
    }
    #pragma unroll
    for (int kd = 0; kd < 12; kd++)
        g_Y[((size_t)(b * 32 + o) * 12 + kd) * 576 + mhw] = acc[kd];
}

// ---------------- I1: inverse DFT along H ----------------
// block = (b*O+o)*12+kd, 256 threads
__global__ void k_i1() {
    __shared__ float2 Ys[576];
    __shared__ float2 E[64];
    int t = threadIdx.x;
    initE(E, t, 256);
    int bo = blockIdx.x / MD, kd = blockIdx.x % MD;
    for (int i = t; i < 576; i += 256)
        Ys[i] = g_Y[(size_t)(bo * MD + kd) * 576 + i];
    __syncthreads();
    int h = t & 63, kwg = t >> 6;
    float2 acc[6];
    #pragma unroll
    for (int u = 0; u < 6; u++) acc[u] = make_float2(0.f, 0.f);
    for (int kh = 0; kh < 24; kh++) {
        int khi = kh + (kh >= 12 ? 40 : 0);
        float2 e = E[(khi * h) & 63];
        #pragma unroll
        for (int u = 0; u < 6; u++) {
            float2 a = Ys[kh * 24 + kwg * 6 + u];
            acc[u].x = fmaf(a.x, e.x, fmaf(-a.y, e.y, acc[u].x));
            acc[u].y = fmaf(a.x, e.y, fmaf( a.y, e.x, acc[u].y));
        }
    }
    #pragma unroll
    for (int u = 0; u < 6; u++)
        g_Z1[((size_t)(bo * 64 + h) * MD + kd) * 24 + kwg * 6 + u] = acc[u];
}

// ---------------- I2: inverse DFT along W ----------------
// block = (b*O+o)*64+h, 256 threads
__global__ void k_i2() {
    __shared__ float2 Zs[288];    // [kd][kw]
    __shared__ float2 E[64];
    int t = threadIdx.x;
    initE(E, t, 256);
    size_t boh = blockIdx.x;
    for (int i = t; i < 288; i += 256)
        Zs[i] = g_Z1[boh * 288 + i];
    __syncthreads();
    int w = t & 63, kdg = t >> 6;
    float2 acc[3];
    #pragma unroll
    for (int u = 0; u < 3; u++) acc[u] = make_float2(0.f, 0.f);
    for (int kw = 0; kw < 24; kw++) {
        int kwi = kw + (kw >= 12 ? 40 : 0);
        float2 e = E[(kwi * w) & 63];
        #pragma unroll
        for (int u = 0; u < 3; u++) {
            float2 a = Zs[(kdg * 3 + u) * 24 + kw];
            acc[u].x = fmaf(a.x, e.x, fmaf(-a.y, e.y, acc[u].x));
            acc[u].y = fmaf(a.x, e.y, fmaf( a.y, e.x, acc[u].y));
        }
    }
    #pragma unroll
    for (int u = 0; u < 3; u++)
        g_Z2[(boh * 64 + w) * MD + kdg * 3 + u] = acc[u];
}

// ---------------- I3: inverse real DFT along D + corr epilogue ----------------
// block = (b*O+o)*64+h, 256 threads
__global__ void k_i3(float* __restrict__ out) {
    __shared__ float2 Zs[768];    // [w][kd]
    __shared__ float2 E[64];
    int t = threadIdx.x;
    initE(E, t, 256);
    size_t boh = blockIdx.x;
    for (int i = t; i < 768; i += 256)
        Zs[i] = g_Z2[boh * 768 + i];
    __syncthreads();
    int d = t & 63, wg = t >> 6;
    int b = blockIdx.x >> 11;              // /(32*64)
    int o = (blockIdx.x >> 6) & 31;
    float cv = g_CORR[(b * 32 + o) * 64 + d];
    float2 e[11];
    #pragma unroll
    for (int k = 1; k <= 11; k++) {
        float2 ee = E[(k * d) & 63];
        e[k-1] = make_float2(2.f * ee.x, 2.f * ee.y);
    }
    const float SC = 1.0f / 262144.0f;     // 1/64^3
    float* orow = out + boh * 4096;
    #pragma unroll 4
    for (int j = 0; j < 16; j++) {
        int w = wg * 16 + j;
        const float2* z = &Zs[w * 12];
        float acc = z[0].x;
        #pragma unroll
        for (int k = 1; k <= 11; k++) {
            float2 zz = z[k];
            acc = fmaf(zz.x, e[k-1].x, fmaf(-zz.y, e[k-1].y, acc));
        }
        orow[w * 64 + d] = fmaf(SC, acc, cv);
    }
}

// ---------------- CK1: Chebyshev-Fourier features ----------------
// block = b*8 + dchunk (32 blocks), 256 threads: t -> (c = t/8, dl = t&7)
__global__ void k_ck1(const float* __restrict__ x) {
    __shared__ float2 E[64];
    int t = threadIdx.x;
    initE(E, t, 256);
    __syncthreads();
    int b = blockIdx.x >> 3, dc = blockIdx.x & 7;
    int c = t >> 3, d = dc * 8 + (t & 7);
    float ar[9], ai[9];
    #pragma unroll
    for (int i = 0; i < 9; i++) { ar[i] = 0.f; ai[i] = 0.f; }
    for (int s = 0; s < 8; s++) {
        float ts = -1.0f + (2.0f / 7.0f) * s;
        float p1 = ts, p2 = 2.0f * ts * ts - 1.0f;
        const float* base = x + ((size_t)(b * 32 + c) * 64 + s) * 4096 + d;
        for (int w = 0; w < 64; w++) {
            float xv = base[w * 64];
            float2 e1 = E[w];
            float2 e2 = E[(2 * w) & 63];
            float xm0 = xv, xm1 = xv * p1, xm2 = xv * p2;
            ar[0] += xm0;
            ar[1] = fmaf(xm0, e1.x, ar[1]); ai[1] = fmaf(-xm0, e1.y, ai[1]);
            ar[2] = fmaf(xm0, e2.x, ar[2]); ai[2] = fmaf(-xm0, e2.y, ai[2]);
            ar[3] += xm1;
            ar[4] = fmaf(xm1, e1.x, ar[4]); ai[4] = fmaf(-xm1, e1.y, ai[4]);
            ar[5] = fmaf(xm1, e2.x, ar[5]); ai[5] = fmaf(-xm1, e2.y, ai[5]);
            ar[6] += xm2;
            ar[7] = fmaf(xm2, e1.x, ar[7]); ai[7] = fmaf(-xm2, e1.y, ai[7]);
            ar[8] = fmaf(xm2, e2.x, ar[8]); ai[8] = fmaf(-xm2, e2.y, ai[8]);
        }
    }
    int n = b * 64 + d;
    float* dst = g_CFT + (size_t)n * 576 + c * 18;   // (c*3+m)*3+kw, *2
    #pragma unroll
    for (int i = 0; i < 9; i++) {
        dst[i * 2    ] = ar[i] * 0.125f;
        dst[i * 2 + 1] = ai[i] * 0.125f;
    }
}

// ---------------- CK2: MLP (576 -> 128 gelu -> 32), scaled ----------------
// block = n (256 blocks), 128 threads
__global__ void k_ck2(const float* __restrict__ W1, const float* __restrict__ b1,
                      const float* __restrict__ W2, const float* __restrict__ b2,
                      const float* __restrict__ corr_scale) {
    __shared__ float fl[576];
    __shared__ float hb[128];
    int n = blockIdx.x, t = threadIdx.x;
    for (int i = t; i < 576; i += 128) fl[i] = g_CFT[(size_t)n * 576 + i];
    __syncthreads();
    float acc = b1[t];
    #pragma unroll 4
    for (int k = 0; k < 576; k++)
        acc = fmaf(fl[k], W1[(size_t)k * 128 + t], acc);
    hb[t] = 0.5f * acc * (1.0f + erff(acc * 0.70710678118654752f));
    __syncthreads();
    if (t < 32) {
        float a2 = b2[t];
        #pragma unroll 4
        for (int k = 0; k < 128; k++)
            a2 = fmaf(hb[k], W2[k * 32 + t], a2);
        int b = n >> 6, d = n & 63;
        g_CORR[(b * 32 + t) * 64 + d] = a2 * corr_scale[0];
    }
}

// ---------------- launch ----------------
extern "C" void kernel_launch(void* const* d_in, const int* in_sizes, int n_in,
                              void* d_out, int out_size) {
    const float* x    = (const float*)d_in[0];
    const float* w1re = (const float*)d_in[1];
    const float* w1im = (const float*)d_in[2];
    const float* w2re = (const float*)d_in[3];
    const float* w2im = (const float*)d_in[4];
    const float* w3re = (const float*)d_in[5];
    const float* w3im = (const float*)d_in[6];
    const float* w4re = (const float*)d_in[7];
    const float* w4im = (const float*)d_in[8];
    const float* W1   = (const float*)d_in[9];
    const float* b1   = (const float*)d_in[10];
    const float* W2   = (const float*)d_in[11];
    const float* b2   = (const float*)d_in[12];
    const float* cs   = (const float*)d_in[13];
    float* out = (float*)d_out;

    static int smem_set = 0;
    const int mix_smem = 24576 * 4 + 1536 * 8;   // 110,592 B
    if (!smem_set) {
        cudaFuncSetAttribute(k_mix, cudaFuncAttributeMaxDynamicSharedMemorySize, mix_smem);
        smem_set = 1;
    }

    // correction branch (independent of FNO chain until i3)
    k_ck1<<<32, 256>>>(x);
    k_ck2<<<256, 128>>>(W1, b1, W2, b2, cs);

    // FNO chain
    k_f1<<<Bn*Cn*Hn, 256>>>(x);
    k_f2<<<Bn*Cn*MD, 256>>>();
    k_f3<<<Bn*Cn*MD, 288>>>();
    k_mix<<<576, 128, mix_smem>>>(w1re, w1im, w2re, w2im, w3re, w3im, w4re, w4im);
    k_i1<<<Bn*On*MD, 256>>>();
    k_i2<<<Bn*On*Hn, 256>>>();
    k_i3<<<Bn*On*Hn, 256>>>(out);
}